// round 10
// baseline (speedup 1.0000x reference)
#include <cuda_runtime.h>
#include <cstdint>
#include <math.h>

#define NEG_INF   (-3.4028234663852886e38f)
#define NBINS     4096
#define CAPA      2048
#define CAPB      1024
#define CAPP      4096
#define NTHREADS  1024

struct Ctl {
  float temp, pres, freq, rep, topp, tempEff;
  float rcpRep, rcpTemp;
  int   outLen, kk, nStop, mnl, hasStop;
  int   stop[8];
  float lseOff, Ssum;
  int   binSel;
  int   nA, nB, nAc, nBc, mCount, nPend;
  unsigned long long bestKey;
  uint32_t thrA;
  float tBf, tRejf;
  float red[32];
  uint32_t chunk[64];
};

// monotone float <-> uint32 mapping (total order)
__device__ __forceinline__ uint32_t fmap(float f) {
  uint32_t u = __float_as_uint(f);
  return u ^ ((u & 0x80000000u) ? 0xFFFFFFFFu : 0x80000000u);
}
__device__ __forceinline__ float funmap(uint32_t u) {
  uint32_t b = (u & 0x80000000u) ? (u ^ 0x80000000u) : ~u;
  return __uint_as_float(b);
}

// penalties + temperature pipeline (identical everywhere it is evaluated)
__device__ __forceinline__ float proc_cp(float raw, int v, int cnt, int pb, const Ctl& s) {
  float x = raw;
  if (s.hasStop) {
#pragma unroll
    for (int i = 0; i < 8; i++)
      if (i < s.nStop && v == s.stop[i]) x = NEG_INF;
  }
  bool outm = cnt > 0;
  bool seen = outm || (pb != 0);
  float scale = seen ? ((x > 0.0f) ? s.rcpRep : s.rep) : 1.0f;
  x = x * scale;
  x = x - s.freq * (float)cnt;
  if (outm) x = x - s.pres;
  return x * s.rcpTemp;
}

// largest bin beta with (#subset elements in bins >= beta) >= need
__device__ int select_bin(const uint32_t* hist, int need, Ctl& s) {
  if (threadIdx.x < 64) {
    uint32_t sum = 0;
    int base = (int)threadIdx.x << 6;
    for (int i = 0; i < 64; i++) sum += hist[base + i];
    s.chunk[threadIdx.x] = sum;
  }
  __syncthreads();
  if (threadIdx.x == 0) {
    long long acc = 0;
    int bin = 0;
    for (int c = 63; c >= 0; c--) {
      long long nacc = acc + (long long)s.chunk[c];
      if (nacc >= need) {
        long long a2 = acc;
        bin = c << 6;
        for (int bi = (c << 6) + 63; bi >= (c << 6); bi--) {
          a2 += (long long)hist[bi];
          if (a2 >= need) { bin = bi; break; }
        }
        break;
      }
      acc = nacc;
    }
    s.binSel = bin;
  }
  __syncthreads();
  return s.binSel;
}

// block-cooperative descending bitonic sort, n = pow2
__device__ void bitonic_desc(unsigned long long* a, int n) {
  for (int k = 2; k <= n; k <<= 1) {
    for (int j = k >> 1; j > 0; j >>= 1) {
      __syncthreads();
      for (int i = (int)threadIdx.x; i < n; i += NTHREADS) {
        int l = i ^ j;
        if (l > i) {
          unsigned long long ai = a[i], al = a[l];
          bool descSeg = ((i & k) == 0);
          bool doSwap = descSeg ? (ai < al) : (ai > al);
          if (doSwap) { a[i] = al; a[l] = ai; }
        }
      }
    }
  }
  __syncthreads();
}

// Threefry-2x32-20, JAX partitionable counter mode, key (0,42); out = out0^out1.
__device__ __forceinline__ float gumbel_jax(uint32_t idx) {
  uint32_t x0 = 0u, x1 = idx;
  const uint32_t k0 = 0u, k1 = 42u;
  const uint32_t k2 = k0 ^ k1 ^ 0x1BD11BDAu;
  x0 += k0; x1 += k1;
#define TFR(r) { x0 += x1; x1 = __funnelshift_l(x1, x1, (r)); x1 ^= x0; }
  TFR(13) TFR(15) TFR(26) TFR(6)   x0 += k1; x1 += k2 + 1u;
  TFR(17) TFR(29) TFR(16) TFR(24)  x0 += k2; x1 += k0 + 2u;
  TFR(13) TFR(15) TFR(26) TFR(6)   x0 += k0; x1 += k1 + 3u;
  TFR(17) TFR(29) TFR(16) TFR(24)  x0 += k1; x1 += k2 + 4u;
  TFR(13) TFR(15) TFR(26) TFR(6)   x0 += k2; x1 += k0 + 5u;
#undef TFR
  uint32_t bits = x0 ^ x1;
  float x = __uint_as_float((bits >> 9) | 0x3F800000u) - 1.0f;
  float u = fmaxf(1e-10f, x + 1e-10f);
  return -logf(-logf(u));
}

__global__ __launch_bounds__(NTHREADS, 1)
void sampler_kernel(const float* __restrict__ logits,
                    const float* __restrict__ temperature,
                    const float* __restrict__ presence,
                    const float* __restrict__ frequency,
                    const float* __restrict__ repetition,
                    const float* __restrict__ top_p,
                    const int*   __restrict__ prompt_ids,
                    const int*   __restrict__ output_ids,
                    const int*   __restrict__ output_lens,
                    const int*   __restrict__ stop_ids,
                    const int*   __restrict__ min_tokens,
                    const int*   __restrict__ top_k,
                    const int*   __restrict__ mnl_ptr,
                    float*       __restrict__ out,
                    int B, int V, int P, int O, int nStopIn) {
  extern __shared__ uint32_t dsm[];
  __shared__ Ctl s;

  const int b    = blockIdx.x;
  const int tid  = (int)threadIdx.x;
  const int lane = tid & 31;
  const int wid  = tid >> 5;

  const int cntWords = (V + 3) >> 2;
  const int pbWords  = (V + 31) >> 5;
  uint32_t* cntW  = dsm;
  uint32_t* pbits = cntW + cntWords;
  uint32_t* histP = pbits + pbWords;
  uint32_t* histR = histP + NBINS;
  int wordsBefore = cntWords + pbWords + 2 * NBINS;
  if (wordsBefore & 1) wordsBefore++;
  unsigned long long* candA = (unsigned long long*)(dsm + wordsBefore);
  unsigned long long* candB = candA + CAPA;
  uint32_t* pend   = (uint32_t*)(candB + CAPB);
  float*    eArr    = (float*)histP;   // reuse after histograms consumed
  uint32_t* keepArr = histR;           // reuse after histograms consumed

  // ---- phase 0: zero smem + row scalars ----
  for (int i = tid; i < cntWords; i += NTHREADS) cntW[i] = 0u;
  for (int i = tid; i < pbWords;  i += NTHREADS) pbits[i] = 0u;
  for (int i = tid; i < NBINS;    i += NTHREADS) { histP[i] = 0u; histR[i] = 0u; }
  if (tid == 0) {
    s.nA = 0; s.nB = 0; s.nPend = 0;
    s.temp = temperature[b]; s.pres = presence[b]; s.freq = frequency[b];
    s.rep  = repetition[b];  s.topp = top_p[b];
    s.tempEff = (s.temp < 1e-5f) ? 1.0f : s.temp;
    s.rcpRep  = 1.0f / s.rep;
    s.rcpTemp = 1.0f / s.tempEff;
    s.outLen  = output_lens[b];
    int pen   = (s.outLen < min_tokens[b]) ? 1 : 0;
    int ns    = nStopIn > 8 ? 8 : nStopIn;
    s.nStop   = ns;
    s.hasStop = (pen && ns > 0) ? 1 : 0;
    for (int i = 0; i < ns; i++) s.stop[i] = pen ? stop_ids[b * nStopIn + i] : -1;
    s.kk  = top_k[b];
    s.mnl = mnl_ptr ? mnl_ptr[0] : 20;
  }
  __syncthreads();

  // ---- phase 0b: scatter prompt mask + output counts ----
  for (int i = tid; i < P; i += NTHREADS) {
    int t = prompt_ids[(size_t)b * P + i];
    atomicOr(&pbits[t >> 5], 1u << (t & 31));
  }
  {
    int ol = s.outLen;
    for (int i = tid; i < O; i += NTHREADS) {
      if (i < ol) {
        int t = output_ids[(size_t)b * O + i];
        atomicAdd(&cntW[t >> 2], 1u << ((t & 3) * 8));
      }
    }
  }
  __syncthreads();

  const float* rowL = logits + (size_t)b * V;
  const float4* row4 = (const float4*)rowL;
  const int nF4 = V >> 2;
  int CH = nF4 >> 3;            // leading chunk (subset used for histograms)
  if (CH < 1) CH = nF4;
  float a0 = 0.f, a1 = 0.f, a2 = 0.f, a3 = 0.f;
  float b0 = 0.f, b1 = 0.f, b2 = 0.f, b3 = 0.f;

  // ---- phase A: leading chunk -> expsum (all) + histograms (even q only) ----
  for (int j = tid; j < CH; j += NTHREADS) {
    float4 f = row4[j];
    a0 += __expf(f.x); a1 += __expf(f.y);
    a2 += __expf(f.z); a3 += __expf(f.w);
    uint32_t cw = cntW[j];
    uint32_t pw = pbits[j >> 3];
    float vals[4] = {f.x, f.y, f.z, f.w};
#pragma unroll
    for (int q = 0; q < 4; q += 2) {   // histogram a 1/2 subset of the chunk
      int v = (j << 2) + q;
      int cnt = (int)((cw >> (q * 8)) & 0xFFu);
      int pb  = (int)((pw >> (((j & 7) << 2) + q)) & 1u);
      float px = proc_cp(vals[q], v, cnt, pb, s);
      atomicAdd(&histR[fmap(vals[q]) >> 20], 1u);
      atomicAdd(&histP[fmap(px)      >> 20], 1u);
    }
  }
  __syncthreads();

  // ---- thresholds from chunk histograms ----
  int kneed = s.kk; if (kneed < 1) kneed = 1; if (kneed > V) kneed = V;
  int binA = select_bin(histP, kneed, s);
  int mnl  = s.mnl;
  int binR = select_bin(histR, mnl, s);

  if (tid == 0) {
    s.thrA = (uint32_t)binA << 20;
    s.tBf  = funmap((uint32_t)binR << 20);
    float tA = funmap(s.thrA);   // lower edge of top-k bin (processed domain)
    float rejf = -INFINITY;      // -inf => everything takes the slow path
    if (tA > 0.0f && s.rep >= 1.0f && s.freq >= 0.0f && s.pres >= 0.0f) {
      float rr = tA * s.tempEff * 0.99f;
      if (rr > 0.0f) rejf = rr;
    }
    s.tRejf = rejf;
  }
  __syncthreads();
  const float tBf   = s.tBf;
  const float tRejf = s.tRejf;
  const float tMin  = fminf(tBf, tRejf);
  uint32_t thrA = s.thrA;

  // full candidate check for one quad (run in the dense drain, or as overflow fallback)
  auto check4 = [&](float4 f, int jj) {
    float vals[4] = {f.x, f.y, f.z, f.w};
#pragma unroll
    for (int q = 0; q < 4; q++) {
      float raw = vals[q];
      int v = (jj << 2) + q;
      if (raw >= tBf) {
        int p = atomicAdd(&s.nB, 1);
        if (p < CAPB) candB[p] = ((unsigned long long)fmap(raw) << 32) | (uint32_t)(~(uint32_t)v);
      }
      if (raw >= tRejf) {
        uint32_t cw = cntW[jj];
        uint32_t pw = pbits[jj >> 3];
        int cnt = (int)((cw >> (q * 8)) & 0xFFu);
        int pb  = (int)((pw >> (((jj & 7) << 2) + q)) & 1u);
        float px = proc_cp(raw, v, cnt, pb, s);
        uint32_t mp = fmap(px);
        if (mp >= thrA) {
          int p = atomicAdd(&s.nA, 1);
          if (p < CAPA) candA[p] = ((unsigned long long)mp << 32) | (uint32_t)(~(uint32_t)v);
        }
      }
    }
  };

  // cheap inline push: defer the heavy work to a convergent drain loop
  auto push_pend = [&](float4 f, int jj) {
    int p = atomicAdd(&s.nPend, 1);
    if (p < CAPP) pend[p] = (uint32_t)jj;
    else          check4(f, jj);   // overflow fallback (rare), stays correct
  };

  // ---- phase B: remaining 7/8 of row -> fused expsum + pend-push, unroll x4 ----
  int j = CH + tid;
  for (; j + 3 * NTHREADS < nF4; j += 4 * NTHREADS) {
    float4 f0 = row4[j];
    float4 f1 = row4[j + NTHREADS];
    float4 f2 = row4[j + 2 * NTHREADS];
    float4 f3 = row4[j + 3 * NTHREADS];
    a0 += __expf(f0.x); a1 += __expf(f0.y); a2 += __expf(f0.z); a3 += __expf(f0.w);
    b0 += __expf(f1.x); b1 += __expf(f1.y); b2 += __expf(f1.z); b3 += __expf(f1.w);
    a0 += __expf(f2.x); a1 += __expf(f2.y); a2 += __expf(f2.z); a3 += __expf(f2.w);
    b0 += __expf(f3.x); b1 += __expf(f3.y); b2 += __expf(f3.z); b3 += __expf(f3.w);
    float mx0 = fmaxf(fmaxf(f0.x, f0.y), fmaxf(f0.z, f0.w));
    float mx1 = fmaxf(fmaxf(f1.x, f1.y), fmaxf(f1.z, f1.w));
    float mx2 = fmaxf(fmaxf(f2.x, f2.y), fmaxf(f2.z, f2.w));
    float mx3 = fmaxf(fmaxf(f3.x, f3.y), fmaxf(f3.z, f3.w));
    if (mx0 >= tMin) push_pend(f0, j);
    if (mx1 >= tMin) push_pend(f1, j + NTHREADS);
    if (mx2 >= tMin) push_pend(f2, j + 2 * NTHREADS);
    if (mx3 >= tMin) push_pend(f3, j + 3 * NTHREADS);
  }
  for (; j < nF4; j += NTHREADS) {
    float4 f = row4[j];
    a0 += __expf(f.x); a1 += __expf(f.y);
    a2 += __expf(f.z); a3 += __expf(f.w);
    float mx = fmaxf(fmaxf(f.x, f.y), fmaxf(f.z, f.w));
    if (mx >= tMin) push_pend(f, j);
  }

  // ---- phase C: scan the leading chunk for candidates (L1/L2 resident) ----
  for (int jc = tid; jc < CH; jc += NTHREADS) {
    float4 f = row4[jc];
    float mx = fmaxf(fmaxf(f.x, f.y), fmaxf(f.z, f.w));
    if (mx >= tMin) push_pend(f, jc);
  }

  // ---- tail (V % 4): expsum + inline collection ----
  for (int v = (nF4 << 2) + tid; v < V; v += NTHREADS) {
    float raw = rowL[v];
    a0 += __expf(raw);
    if (raw >= tBf) {
      int p = atomicAdd(&s.nB, 1);
      if (p < CAPB) candB[p] = ((unsigned long long)fmap(raw) << 32) | (uint32_t)(~(uint32_t)v);
    }
    if (raw >= tRejf) {
      uint32_t cw = cntW[v >> 2];
      uint32_t pw = pbits[v >> 5];
      int cnt = (int)((cw >> ((v & 3) * 8)) & 0xFFu);
      int pb  = (int)((pw >> (v & 31)) & 1u);
      float px = proc_cp(raw, v, cnt, pb, s);
      uint32_t mp = fmap(px);
      if (mp >= thrA) {
        int p = atomicAdd(&s.nA, 1);
        if (p < CAPA) candA[p] = ((unsigned long long)mp << 32) | (uint32_t)(~(uint32_t)v);
      }
    }
  }
  __syncthreads();

  // ---- drain pending quads (dense, convergent; loads hit L2) ----
  {
    int np = s.nPend < CAPP ? s.nPend : CAPP;
    for (int i = tid; i < np; i += NTHREADS) {
      int jj = (int)pend[i];
      check4(row4[jj], jj);
    }
  }

  // ---- expsum block reduction -> lse ----
  {
    float sl = ((a0 + a1) + (a2 + a3)) + ((b0 + b1) + (b2 + b3));
    for (int off = 16; off; off >>= 1) sl += __shfl_down_sync(0xFFFFFFFFu, sl, off);
    if (lane == 0) s.red[wid] = sl;
  }
  __syncthreads();
  if (wid == 0) {
    float t2 = s.red[lane];
    for (int off = 16; off; off >>= 1) t2 += __shfl_down_sync(0xFFFFFFFFu, t2, off);
    if (lane == 0) s.lseOff = logf(t2);
  }
  __syncthreads();

  // ---- overflow guard (practically unreachable): tighten bin and recollect A ----
  while (s.nA > CAPA) {
    __syncthreads();
    if (tid == 0) { binA = binA < 4095 ? binA + 1 : 4095; s.thrA = (uint32_t)binA << 20; s.nA = 0; }
    __syncthreads();
    thrA = s.thrA;
    for (int v = tid; v < V; v += NTHREADS) {
      float raw = rowL[v];
      if (raw >= tRejf) {
        uint32_t cw = cntW[v >> 2];
        uint32_t pw = pbits[v >> 5];
        int cnt = (int)((cw >> ((v & 3) * 8)) & 0xFFu);
        int pb  = (int)((pw >> (v & 31)) & 1u);
        float px = proc_cp(raw, v, cnt, pb, s);
        uint32_t mp = fmap(px);
        if (mp >= thrA) {
          int p = atomicAdd(&s.nA, 1);
          if (p < CAPA) candA[p] = ((unsigned long long)mp << 32) | (uint32_t)(~(uint32_t)v);
        }
      }
    }
    __syncthreads();
    if (binA >= 4095) break;
  }
  __syncthreads();

  if (tid == 0) {
    s.nAc = s.nA < CAPA ? s.nA : CAPA;
    s.nBc = s.nB < CAPB ? s.nB : CAPB;
  }
  __syncthreads();
  const int nAc = s.nAc, nBc = s.nBc;

  // ---- sort candidates descending by (value, index asc) ----
  int sortNA = 2; while (sortNA < nAc) sortNA <<= 1;
  for (int i = nAc + tid; i < sortNA; i += NTHREADS) candA[i] = 0ull;
  int sortNB = 2; while (sortNB < nBc) sortNB <<= 1;
  for (int i = nBc + tid; i < sortNB; i += NTHREADS) candB[i] = 0ull;
  __syncthreads();
  bitonic_desc(candA, sortNA);
  bitonic_desc(candB, sortNB);

  // ---- top-k boundary + survivor count ----
  if (tid == 0) {
    int k = kneed; if (k > nAc) k = nAc; if (k < 1) k = 1;
    uint32_t kth = (uint32_t)(candA[k - 1] >> 32);
    int m = k;
    while (m < nAc && (uint32_t)(candA[m] >> 32) >= kth) m++;
    if (m > CAPA) m = CAPA;
    s.mCount  = m;
    s.bestKey = 0ull;
  }
  __syncthreads();
  const int m = s.mCount;
  const float maxV = funmap((uint32_t)(candA[0] >> 32));

  // ---- softmax over survivors ----
  float local = 0.0f;
  for (int jj = tid; jj < m; jj += NTHREADS) {
    float vj = funmap((uint32_t)(candA[jj] >> 32));
    float e  = expf(vj - maxV);
    eArr[jj] = e;
    local += e;
  }
  for (int off = 16; off; off >>= 1) local += __shfl_down_sync(0xFFFFFFFFu, local, off);
  if (lane == 0) s.red[wid] = local;
  __syncthreads();
  if (wid == 0) {
    float t2 = s.red[lane];
    for (int off = 16; off; off >>= 1) t2 += __shfl_down_sync(0xFFFFFFFFu, t2, off);
    if (lane == 0) s.Ssum = t2;
  }
  __syncthreads();

  // ---- top-p keep mask via parallel suffix scan (reversed prefix) ----
  {
    const float limit = 1.0f - s.topp;
    const float Ssum  = s.Ssum;
    const int   c     = (m + NTHREADS - 1) / NTHREADS;  // 1 or 2
    float ch[2]; float csum = 0.0f;
#pragma unroll
    for (int i = 0; i < 2; i++) {
      float e = 0.0f;
      if (i < c) {
        int r = tid * c + i;
        if (r < m) e = eArr[m - 1 - r] / Ssum;
      }
      ch[i] = e; csum += e;
    }
    float inc = csum;
    for (int off = 1; off < 32; off <<= 1) {
      float n = __shfl_up_sync(0xFFFFFFFFu, inc, off);
      if (lane >= off) inc += n;
    }
    float wexcl = inc - csum;
    if (lane == 31) s.red[wid] = inc;
    __syncthreads();
    if (wid == 0) {
      float wv = s.red[lane];
      float wi = wv;
      for (int off = 1; off < 32; off <<= 1) {
        float n = __shfl_up_sync(0xFFFFFFFFu, wi, off);
        if (lane >= off) wi += n;
      }
      s.red[lane] = wi - wv;
    }
    __syncthreads();
    float base = s.red[wid] + wexcl;
    float run = 0.0f;
#pragma unroll
    for (int i = 0; i < 2; i++) {
      if (i < c) {
        int r = tid * c + i;
        run += ch[i];
        if (r < m) {
          int jj = m - 1 - r;
          float T = base + run;
          keepArr[jj] = (jj == 0 || T > limit) ? 1u : 0u;
        }
      }
    }
  }
  __syncthreads();

  // ---- gumbel argmax over kept survivors ----
  for (int jj = tid; jj < m; jj += NTHREADS) {
    if (keepArr[jj]) {
      uint32_t idxc = (uint32_t)(candA[jj] & 0xFFFFFFFFull);
      int v = (int)(~idxc);
      float vj = funmap((uint32_t)(candA[jj] >> 32));
      float g  = gumbel_jax((uint32_t)(b * V + v));
      float cand = vj + g;
      unsigned long long key = ((unsigned long long)fmap(cand) << 32) | (uint32_t)(~(uint32_t)v);
      atomicMax(&s.bestKey, key);
    }
  }
  __syncthreads();

  // ---- outputs: [sampled(B)] [topk_logprobs(B*mnl)] [topk_indices(B*mnl)] f32 ----
  if (tid == 0) {
    int greedy  = (int)(~(uint32_t)(candA[0] & 0xFFFFFFFFull));
    int randomS = (int)(~(uint32_t)(s.bestKey & 0xFFFFFFFFull));
    int sampled = (s.temp < 1e-5f) ? greedy : randomS;
    out[b] = (float)sampled;
  }
  for (int jj = tid; jj < mnl; jj += NTHREADS) {
    float val; int v;
    if (jj < nBc) {
      unsigned long long key = candB[jj];
      v   = (int)(~(uint32_t)(key & 0xFFFFFFFFull));
      val = funmap((uint32_t)(key >> 32));
    } else { v = 0; val = NEG_INF; }
    out[(size_t)B + (size_t)b * mnl + jj]                   = val - s.lseOff;
    out[(size_t)B + (size_t)B * mnl + (size_t)b * mnl + jj] = (float)v;
  }
}

extern "C" void kernel_launch(void* const* d_in, const int* in_sizes, int n_in,
                              void* d_out, int out_size) {
  const float* logits      = (const float*)d_in[0];
  const float* temperature = (const float*)d_in[1];
  const float* presence    = (const float*)d_in[2];
  const float* frequency   = (const float*)d_in[3];
  const float* repetition  = (const float*)d_in[4];
  const float* top_p       = (const float*)d_in[5];
  const int*   prompt_ids  = (const int*)d_in[6];
  const int*   output_ids  = (const int*)d_in[7];
  const int*   output_lens = (const int*)d_in[8];
  const int*   stop_ids    = (const int*)d_in[9];
  const int*   min_tokens  = (const int*)d_in[10];
  const int*   top_k       = (const int*)d_in[11];
  const int*   mnl_ptr     = (n_in >= 13) ? (const int*)d_in[12] : nullptr;

  const int B = in_sizes[1];
  const int V = in_sizes[0] / B;
  const int P = in_sizes[6] / B;
  const int O = in_sizes[7] / B;
  const int nStop = in_sizes[9] / B;

  int cntWords = (V + 3) >> 2;
  int pbWords  = (V + 31) >> 5;
  int wordsBefore = cntWords + pbWords + 2 * NBINS;
  if (wordsBefore & 1) wordsBefore++;
  size_t smemB = (size_t)wordsBefore * 4 + (size_t)(CAPA + CAPB) * 8 + (size_t)CAPP * 4;

  cudaFuncSetAttribute(sampler_kernel, cudaFuncAttributeMaxDynamicSharedMemorySize, (int)smemB);
  sampler_kernel<<<B, NTHREADS, smemB>>>(
      logits, temperature, presence, frequency, repetition, top_p,
      prompt_ids, output_ids, output_lens, stop_ids, min_tokens, top_k,
      mnl_ptr, (float*)d_out, B, V, P, O, nStop);
}

// round 11
// speedup vs baseline: 1.4794x; 1.4794x over previous
#include <cuda_runtime.h>
#include <cstdint>
#include <math.h>

#define NEG_INF   (-3.4028234663852886e38f)
#define NBINS     4096
#define CAPA      2048
#define CAPB      1024
#define CAPP      4096
#define NTHREADS  1024

struct Ctl {
  float temp, pres, freq, rep, topp, tempEff;
  float rcpRep, rcpTemp;
  int   outLen, kk, nStop, mnl, hasStop;
  int   stop[8];
  float lseOff, Ssum;
  int   binSel;
  int   nA, nB, nAc, nBc, mCount, nPend;
  unsigned long long bestKey;
  uint32_t thrA;
  float tBf, tRejf;
  float red[32];
  uint32_t chunk[64];
};

// monotone float <-> uint32 mapping (total order)
__device__ __forceinline__ uint32_t fmap(float f) {
  uint32_t u = __float_as_uint(f);
  return u ^ ((u & 0x80000000u) ? 0xFFFFFFFFu : 0x80000000u);
}
__device__ __forceinline__ float funmap(uint32_t u) {
  uint32_t b = (u & 0x80000000u) ? (u ^ 0x80000000u) : ~u;
  return __uint_as_float(b);
}

// penalties + temperature pipeline (identical everywhere it is evaluated)
__device__ __forceinline__ float proc_cp(float raw, int v, int cnt, int pb, const Ctl& s) {
  float x = raw;
  if (s.hasStop) {
#pragma unroll
    for (int i = 0; i < 8; i++)
      if (i < s.nStop && v == s.stop[i]) x = NEG_INF;
  }
  bool outm = cnt > 0;
  bool seen = outm || (pb != 0);
  float scale = seen ? ((x > 0.0f) ? s.rcpRep : s.rep) : 1.0f;
  x = x * scale;
  x = x - s.freq * (float)cnt;
  if (outm) x = x - s.pres;
  return x * s.rcpTemp;
}

// largest bin beta with (#subset elements in bins >= beta) >= need
__device__ int select_bin(const uint32_t* hist, int need, Ctl& s) {
  if (threadIdx.x < 64) {
    uint32_t sum = 0;
    int base = (int)threadIdx.x << 6;
    for (int i = 0; i < 64; i++) sum += hist[base + i];
    s.chunk[threadIdx.x] = sum;
  }
  __syncthreads();
  if (threadIdx.x == 0) {
    long long acc = 0;
    int bin = 0;
    for (int c = 63; c >= 0; c--) {
      long long nacc = acc + (long long)s.chunk[c];
      if (nacc >= need) {
        long long a2 = acc;
        bin = c << 6;
        for (int bi = (c << 6) + 63; bi >= (c << 6); bi--) {
          a2 += (long long)hist[bi];
          if (a2 >= need) { bin = bi; break; }
        }
        break;
      }
      acc = nacc;
    }
    s.binSel = bin;
  }
  __syncthreads();
  return s.binSel;
}

// block-cooperative descending bitonic sort, n = pow2
__device__ void bitonic_desc(unsigned long long* a, int n) {
  for (int k = 2; k <= n; k <<= 1) {
    for (int j = k >> 1; j > 0; j >>= 1) {
      __syncthreads();
      for (int i = (int)threadIdx.x; i < n; i += NTHREADS) {
        int l = i ^ j;
        if (l > i) {
          unsigned long long ai = a[i], al = a[l];
          bool descSeg = ((i & k) == 0);
          bool doSwap = descSeg ? (ai < al) : (ai > al);
          if (doSwap) { a[i] = al; a[l] = ai; }
        }
      }
    }
  }
  __syncthreads();
}

// Threefry-2x32-20, JAX partitionable counter mode, key (0,42); out = out0^out1.
__device__ __forceinline__ float gumbel_jax(uint32_t idx) {
  uint32_t x0 = 0u, x1 = idx;
  const uint32_t k0 = 0u, k1 = 42u;
  const uint32_t k2 = k0 ^ k1 ^ 0x1BD11BDAu;
  x0 += k0; x1 += k1;
#define TFR(r) { x0 += x1; x1 = __funnelshift_l(x1, x1, (r)); x1 ^= x0; }
  TFR(13) TFR(15) TFR(26) TFR(6)   x0 += k1; x1 += k2 + 1u;
  TFR(17) TFR(29) TFR(16) TFR(24)  x0 += k2; x1 += k0 + 2u;
  TFR(13) TFR(15) TFR(26) TFR(6)   x0 += k0; x1 += k1 + 3u;
  TFR(17) TFR(29) TFR(16) TFR(24)  x0 += k1; x1 += k2 + 4u;
  TFR(13) TFR(15) TFR(26) TFR(6)   x0 += k2; x1 += k0 + 5u;
#undef TFR
  uint32_t bits = x0 ^ x1;
  float x = __uint_as_float((bits >> 9) | 0x3F800000u) - 1.0f;
  float u = fmaxf(1e-10f, x + 1e-10f);
  return -logf(-logf(u));
}

__global__ __launch_bounds__(NTHREADS, 1)
void sampler_kernel(const float* __restrict__ logits,
                    const float* __restrict__ temperature,
                    const float* __restrict__ presence,
                    const float* __restrict__ frequency,
                    const float* __restrict__ repetition,
                    const float* __restrict__ top_p,
                    const int*   __restrict__ prompt_ids,
                    const int*   __restrict__ output_ids,
                    const int*   __restrict__ output_lens,
                    const int*   __restrict__ stop_ids,
                    const int*   __restrict__ min_tokens,
                    const int*   __restrict__ top_k,
                    const int*   __restrict__ mnl_ptr,
                    float*       __restrict__ out,
                    int B, int V, int P, int O, int nStopIn) {
  extern __shared__ uint32_t dsm[];
  __shared__ Ctl s;

  const int b    = blockIdx.x;
  const int tid  = (int)threadIdx.x;
  const int lane = tid & 31;
  const int wid  = tid >> 5;

  const int cntWords = (V + 3) >> 2;
  const int pbWords  = (V + 31) >> 5;
  uint32_t* cntW  = dsm;
  uint32_t* pbits = cntW + cntWords;
  uint32_t* histP = pbits + pbWords;
  uint32_t* histR = histP + NBINS;
  int wordsBefore = cntWords + pbWords + 2 * NBINS;
  if (wordsBefore & 1) wordsBefore++;
  unsigned long long* candA = (unsigned long long*)(dsm + wordsBefore);
  unsigned long long* candB = candA + CAPA;
  uint32_t* pend   = (uint32_t*)(candB + CAPB);
  float*    eArr    = (float*)histP;   // reuse after histograms consumed
  uint32_t* keepArr = histR;           // reuse after histograms consumed

  // ---- phase 0: zero smem + row scalars ----
  for (int i = tid; i < cntWords; i += NTHREADS) cntW[i] = 0u;
  for (int i = tid; i < pbWords;  i += NTHREADS) pbits[i] = 0u;
  for (int i = tid; i < NBINS;    i += NTHREADS) { histP[i] = 0u; histR[i] = 0u; }
  if (tid == 0) {
    s.nA = 0; s.nB = 0; s.nPend = 0;
    s.temp = temperature[b]; s.pres = presence[b]; s.freq = frequency[b];
    s.rep  = repetition[b];  s.topp = top_p[b];
    s.tempEff = (s.temp < 1e-5f) ? 1.0f : s.temp;
    s.rcpRep  = 1.0f / s.rep;
    s.rcpTemp = 1.0f / s.tempEff;
    s.outLen  = output_lens[b];
    int pen   = (s.outLen < min_tokens[b]) ? 1 : 0;
    int ns    = nStopIn > 8 ? 8 : nStopIn;
    s.nStop   = ns;
    s.hasStop = (pen && ns > 0) ? 1 : 0;
    for (int i = 0; i < ns; i++) s.stop[i] = pen ? stop_ids[b * nStopIn + i] : -1;
    s.kk  = top_k[b];
    s.mnl = mnl_ptr ? mnl_ptr[0] : 20;
  }
  __syncthreads();

  // ---- phase 0b: scatter prompt mask + output counts ----
  for (int i = tid; i < P; i += NTHREADS) {
    int t = prompt_ids[(size_t)b * P + i];
    atomicOr(&pbits[t >> 5], 1u << (t & 31));
  }
  {
    int ol = s.outLen;
    for (int i = tid; i < O; i += NTHREADS) {
      if (i < ol) {
        int t = output_ids[(size_t)b * O + i];
        atomicAdd(&cntW[t >> 2], 1u << ((t & 3) * 8));
      }
    }
  }
  __syncthreads();

  const float* rowL = logits + (size_t)b * V;
  const float4* row4 = (const float4*)rowL;
  const int nF4 = V >> 2;
  int CH = nF4 >> 3;            // leading chunk (subset used for histograms)
  if (CH < 1) CH = nF4;
  float a0 = 0.f, a1 = 0.f, a2 = 0.f, a3 = 0.f;
  float b0 = 0.f, b1 = 0.f, b2 = 0.f, b3 = 0.f;

  // ---- phase A: leading chunk -> expsum + dense histograms (every element) ----
  for (int j = tid; j < CH; j += NTHREADS) {
    float4 f = row4[j];
    a0 += __expf(f.x); a1 += __expf(f.y);
    a2 += __expf(f.z); a3 += __expf(f.w);
    uint32_t cw = cntW[j];
    uint32_t pw = pbits[j >> 3];
    float vals[4] = {f.x, f.y, f.z, f.w};
#pragma unroll
    for (int q = 0; q < 4; q++) {
      int v = (j << 2) + q;
      int cnt = (int)((cw >> (q * 8)) & 0xFFu);
      int pb  = (int)((pw >> (((j & 7) << 2) + q)) & 1u);
      float px = proc_cp(vals[q], v, cnt, pb, s);
      atomicAdd(&histR[fmap(vals[q]) >> 20], 1u);
      atomicAdd(&histP[fmap(px)      >> 20], 1u);
    }
  }
  __syncthreads();

  // ---- thresholds from chunk histograms ----
  int kneed = s.kk; if (kneed < 1) kneed = 1; if (kneed > V) kneed = V;
  int binA = select_bin(histP, kneed, s);
  int mnl  = s.mnl;
  int binR = select_bin(histR, mnl, s);

  if (tid == 0) {
    s.thrA = (uint32_t)binA << 20;
    s.tBf  = funmap((uint32_t)binR << 20);
    float tA = funmap(s.thrA);   // lower edge of top-k bin (processed domain)
    float rejf = -INFINITY;      // -inf => everything takes the slow path
    if (tA > 0.0f && s.rep >= 1.0f && s.freq >= 0.0f && s.pres >= 0.0f) {
      float rr = tA * s.tempEff * 0.99f;
      if (rr > 0.0f) rejf = rr;
    }
    s.tRejf = rejf;
  }
  __syncthreads();
  const float tBf   = s.tBf;
  const float tRejf = s.tRejf;
  const float tMin  = fminf(tBf, tRejf);
  uint32_t thrA = s.thrA;

  // full candidate check for one quad (run in the dense drain, or as overflow fallback)
  auto check4 = [&](float4 f, int jj) {
    float vals[4] = {f.x, f.y, f.z, f.w};
#pragma unroll
    for (int q = 0; q < 4; q++) {
      float raw = vals[q];
      int v = (jj << 2) + q;
      if (raw >= tBf) {
        int p = atomicAdd(&s.nB, 1);
        if (p < CAPB) candB[p] = ((unsigned long long)fmap(raw) << 32) | (uint32_t)(~(uint32_t)v);
      }
      if (raw >= tRejf) {
        uint32_t cw = cntW[jj];
        uint32_t pw = pbits[jj >> 3];
        int cnt = (int)((cw >> (q * 8)) & 0xFFu);
        int pb  = (int)((pw >> (((jj & 7) << 2) + q)) & 1u);
        float px = proc_cp(raw, v, cnt, pb, s);
        uint32_t mp = fmap(px);
        if (mp >= thrA) {
          int p = atomicAdd(&s.nA, 1);
          if (p < CAPA) candA[p] = ((unsigned long long)mp << 32) | (uint32_t)(~(uint32_t)v);
        }
      }
    }
  };

  // cheap inline push: defer the heavy work to a convergent drain loop
  auto push_pend = [&](float4 f, int jj) {
    int p = atomicAdd(&s.nPend, 1);
    if (p < CAPP) pend[p] = (uint32_t)jj;
    else          check4(f, jj);   // overflow fallback (rare), stays correct
  };

  // ---- phase B: remaining 7/8 of row -> fused expsum + pend-push, unroll x2 ----
  int j = CH + tid;
  for (; j + NTHREADS < nF4; j += 2 * NTHREADS) {
    float4 f0 = row4[j];
    float4 f1 = row4[j + NTHREADS];
    a0 += __expf(f0.x); a1 += __expf(f0.y);
    a2 += __expf(f0.z); a3 += __expf(f0.w);
    b0 += __expf(f1.x); b1 += __expf(f1.y);
    b2 += __expf(f1.z); b3 += __expf(f1.w);
    float mx0 = fmaxf(fmaxf(f0.x, f0.y), fmaxf(f0.z, f0.w));
    float mx1 = fmaxf(fmaxf(f1.x, f1.y), fmaxf(f1.z, f1.w));
    if (mx0 >= tMin) push_pend(f0, j);
    if (mx1 >= tMin) push_pend(f1, j + NTHREADS);
  }
  for (; j < nF4; j += NTHREADS) {
    float4 f = row4[j];
    a0 += __expf(f.x); a1 += __expf(f.y);
    a2 += __expf(f.z); a3 += __expf(f.w);
    float mx = fmaxf(fmaxf(f.x, f.y), fmaxf(f.z, f.w));
    if (mx >= tMin) push_pend(f, j);
  }

  // ---- phase C: scan the leading chunk for candidates (L1/L2 resident) ----
  for (int jc = tid; jc < CH; jc += NTHREADS) {
    float4 f = row4[jc];
    float mx = fmaxf(fmaxf(f.x, f.y), fmaxf(f.z, f.w));
    if (mx >= tMin) push_pend(f, jc);
  }

  // ---- tail (V % 4): expsum + inline collection ----
  for (int v = (nF4 << 2) + tid; v < V; v += NTHREADS) {
    float raw = rowL[v];
    a0 += __expf(raw);
    if (raw >= tBf) {
      int p = atomicAdd(&s.nB, 1);
      if (p < CAPB) candB[p] = ((unsigned long long)fmap(raw) << 32) | (uint32_t)(~(uint32_t)v);
    }
    if (raw >= tRejf) {
      uint32_t cw = cntW[v >> 2];
      uint32_t pw = pbits[v >> 5];
      int cnt = (int)((cw >> ((v & 3) * 8)) & 0xFFu);
      int pb  = (int)((pw >> (v & 31)) & 1u);
      float px = proc_cp(raw, v, cnt, pb, s);
      uint32_t mp = fmap(px);
      if (mp >= thrA) {
        int p = atomicAdd(&s.nA, 1);
        if (p < CAPA) candA[p] = ((unsigned long long)mp << 32) | (uint32_t)(~(uint32_t)v);
      }
    }
  }
  __syncthreads();

  // ---- drain pending quads (dense, convergent; loads hit L2) ----
  {
    int np = s.nPend < CAPP ? s.nPend : CAPP;
    for (int i = tid; i < np; i += NTHREADS) {
      int jj = (int)pend[i];
      check4(row4[jj], jj);
    }
  }

  // ---- expsum block reduction -> lse ----
  {
    float sl = ((a0 + a1) + (a2 + a3)) + ((b0 + b1) + (b2 + b3));
    for (int off = 16; off; off >>= 1) sl += __shfl_down_sync(0xFFFFFFFFu, sl, off);
    if (lane == 0) s.red[wid] = sl;
  }
  __syncthreads();
  if (wid == 0) {
    float t2 = s.red[lane];
    for (int off = 16; off; off >>= 1) t2 += __shfl_down_sync(0xFFFFFFFFu, t2, off);
    if (lane == 0) s.lseOff = logf(t2);
  }
  __syncthreads();

  // ---- overflow guard (practically unreachable): tighten bin and recollect A ----
  while (s.nA > CAPA) {
    __syncthreads();
    if (tid == 0) { binA = binA < 4095 ? binA + 1 : 4095; s.thrA = (uint32_t)binA << 20; s.nA = 0; }
    __syncthreads();
    thrA = s.thrA;
    for (int v = tid; v < V; v += NTHREADS) {
      float raw = rowL[v];
      if (raw >= tRejf) {
        uint32_t cw = cntW[v >> 2];
        uint32_t pw = pbits[v >> 5];
        int cnt = (int)((cw >> ((v & 3) * 8)) & 0xFFu);
        int pb  = (int)((pw >> (v & 31)) & 1u);
        float px = proc_cp(raw, v, cnt, pb, s);
        uint32_t mp = fmap(px);
        if (mp >= thrA) {
          int p = atomicAdd(&s.nA, 1);
          if (p < CAPA) candA[p] = ((unsigned long long)mp << 32) | (uint32_t)(~(uint32_t)v);
        }
      }
    }
    __syncthreads();
    if (binA >= 4095) break;
  }
  __syncthreads();

  if (tid == 0) {
    s.nAc = s.nA < CAPA ? s.nA : CAPA;
    s.nBc = s.nB < CAPB ? s.nB : CAPB;
  }
  __syncthreads();
  const int nAc = s.nAc, nBc = s.nBc;

  // ---- sort candidates descending by (value, index asc) ----
  int sortNA = 2; while (sortNA < nAc) sortNA <<= 1;
  for (int i = nAc + tid; i < sortNA; i += NTHREADS) candA[i] = 0ull;
  int sortNB = 2; while (sortNB < nBc) sortNB <<= 1;
  for (int i = nBc + tid; i < sortNB; i += NTHREADS) candB[i] = 0ull;
  __syncthreads();
  bitonic_desc(candA, sortNA);
  bitonic_desc(candB, sortNB);

  // ---- top-k boundary + survivor count ----
  if (tid == 0) {
    int k = kneed; if (k > nAc) k = nAc; if (k < 1) k = 1;
    uint32_t kth = (uint32_t)(candA[k - 1] >> 32);
    int m = k;
    while (m < nAc && (uint32_t)(candA[m] >> 32) >= kth) m++;
    if (m > CAPA) m = CAPA;
    s.mCount  = m;
    s.bestKey = 0ull;
  }
  __syncthreads();
  const int m = s.mCount;
  const float maxV = funmap((uint32_t)(candA[0] >> 32));

  // ---- softmax over survivors ----
  float local = 0.0f;
  for (int jj = tid; jj < m; jj += NTHREADS) {
    float vj = funmap((uint32_t)(candA[jj] >> 32));
    float e  = expf(vj - maxV);
    eArr[jj] = e;
    local += e;
  }
  for (int off = 16; off; off >>= 1) local += __shfl_down_sync(0xFFFFFFFFu, local, off);
  if (lane == 0) s.red[wid] = local;
  __syncthreads();
  if (wid == 0) {
    float t2 = s.red[lane];
    for (int off = 16; off; off >>= 1) t2 += __shfl_down_sync(0xFFFFFFFFu, t2, off);
    if (lane == 0) s.Ssum = t2;
  }
  __syncthreads();

  // ---- top-p keep mask via parallel suffix scan (reversed prefix) ----
  {
    const float limit = 1.0f - s.topp;
    const float Ssum  = s.Ssum;
    const int   c     = (m + NTHREADS - 1) / NTHREADS;  // 1 or 2
    float ch[2]; float csum = 0.0f;
#pragma unroll
    for (int i = 0; i < 2; i++) {
      float e = 0.0f;
      if (i < c) {
        int r = tid * c + i;
        if (r < m) e = eArr[m - 1 - r] / Ssum;
      }
      ch[i] = e; csum += e;
    }
    float inc = csum;
    for (int off = 1; off < 32; off <<= 1) {
      float n = __shfl_up_sync(0xFFFFFFFFu, inc, off);
      if (lane >= off) inc += n;
    }
    float wexcl = inc - csum;
    if (lane == 31) s.red[wid] = inc;
    __syncthreads();
    if (wid == 0) {
      float wv = s.red[lane];
      float wi = wv;
      for (int off = 1; off < 32; off <<= 1) {
        float n = __shfl_up_sync(0xFFFFFFFFu, wi, off);
        if (lane >= off) wi += n;
      }
      s.red[lane] = wi - wv;
    }
    __syncthreads();
    float base = s.red[wid] + wexcl;
    float run = 0.0f;
#pragma unroll
    for (int i = 0; i < 2; i++) {
      if (i < c) {
        int r = tid * c + i;
        run += ch[i];
        if (r < m) {
          int jj = m - 1 - r;
          float T = base + run;
          keepArr[jj] = (jj == 0 || T > limit) ? 1u : 0u;
        }
      }
    }
  }
  __syncthreads();

  // ---- gumbel argmax over kept survivors ----
  for (int jj = tid; jj < m; jj += NTHREADS) {
    if (keepArr[jj]) {
      uint32_t idxc = (uint32_t)(candA[jj] & 0xFFFFFFFFull);
      int v = (int)(~idxc);
      float vj = funmap((uint32_t)(candA[jj] >> 32));
      float g  = gumbel_jax((uint32_t)(b * V + v));
      float cand = vj + g;
      unsigned long long key = ((unsigned long long)fmap(cand) << 32) | (uint32_t)(~(uint32_t)v);
      atomicMax(&s.bestKey, key);
    }
  }
  __syncthreads();

  // ---- outputs: [sampled(B)] [topk_logprobs(B*mnl)] [topk_indices(B*mnl)] f32 ----
  if (tid == 0) {
    int greedy  = (int)(~(uint32_t)(candA[0] & 0xFFFFFFFFull));
    int randomS = (int)(~(uint32_t)(s.bestKey & 0xFFFFFFFFull));
    int sampled = (s.temp < 1e-5f) ? greedy : randomS;
    out[b] = (float)sampled;
  }
  for (int jj = tid; jj < mnl; jj += NTHREADS) {
    float val; int v;
    if (jj < nBc) {
      unsigned long long key = candB[jj];
      v   = (int)(~(uint32_t)(key & 0xFFFFFFFFull));
      val = funmap((uint32_t)(key >> 32));
    } else { v = 0; val = NEG_INF; }
    out[(size_t)B + (size_t)b * mnl + jj]                   = val - s.lseOff;
    out[(size_t)B + (size_t)B * mnl + (size_t)b * mnl + jj] = (float)v;
  }
}

extern "C" void kernel_launch(void* const* d_in, const int* in_sizes, int n_in,
                              void* d_out, int out_size) {
  const float* logits      = (const float*)d_in[0];
  const float* temperature = (const float*)d_in[1];
  const float* presence    = (const float*)d_in[2];
  const float* frequency   = (const float*)d_in[3];
  const float* repetition  = (const float*)d_in[4];
  const float* top_p       = (const float*)d_in[5];
  const int*   prompt_ids  = (const int*)d_in[6];
  const int*   output_ids  = (const int*)d_in[7];
  const int*   output_lens = (const int*)d_in[8];
  const int*   stop_ids    = (const int*)d_in[9];
  const int*   min_tokens  = (const int*)d_in[10];
  const int*   top_k       = (const int*)d_in[11];
  const int*   mnl_ptr     = (n_in >= 13) ? (const int*)d_in[12] : nullptr;

  const int B = in_sizes[1];
  const int V = in_sizes[0] / B;
  const int P = in_sizes[6] / B;
  const int O = in_sizes[7] / B;
  const int nStop = in_sizes[9] / B;

  int cntWords = (V + 3) >> 2;
  int pbWords  = (V + 31) >> 5;
  int wordsBefore = cntWords + pbWords + 2 * NBINS;
  if (wordsBefore & 1) wordsBefore++;
  size_t smemB = (size_t)wordsBefore * 4 + (size_t)(CAPA + CAPB) * 8 + (size_t)CAPP * 4;

  cudaFuncSetAttribute(sampler_kernel, cudaFuncAttributeMaxDynamicSharedMemorySize, (int)smemB);
  sampler_kernel<<<B, NTHREADS, smemB>>>(
      logits, temperature, presence, frequency, repetition, top_p,
      prompt_ids, output_ids, output_lens, stop_ids, min_tokens, top_k,
      mnl_ptr, (float*)d_out, B, V, P, O, nStop);
}